// round 2
// baseline (speedup 1.0000x reference)
#include <cuda_runtime.h>
#include <cstdint>

// Problem constants
#define NSEG 513
#define NBATCH 8
#define HW (1024 * 1024)

#define THREADS 512
#define BLOCKS_PER_BATCH 64
#define PIX_PER_BLOCK (HW / BLOCKS_PER_BATCH)      // 16384
#define VEC_ITERS (PIX_PER_BLOCK / (THREADS * 4))  // 8
#define TOTAL_BLOCKS (BLOCKS_PER_BATCH * NBATCH)   // 512

// Fixed-point packing: [count:12 | clean_q14:26 | pred_q14:26]
#define Q_SCALE 16384.0f
#define FIELD_MASK 0x3FFFFFFull
#define CNT_SHIFT 52
#define CLEAN_SHIFT 26

// Global scratch — zero-initialized at module load; finalize re-zeroes after each
// run so every invocation (correctness run + every graph replay) sees zeros.
__device__ unsigned long long g_hist[NBATCH * NSEG];
__device__ unsigned int g_ticket;

__device__ __forceinline__ unsigned long long pack_pix(float c, float p) {
    unsigned int ci = __float2uint_rn(c * Q_SCALE);
    unsigned int pi = __float2uint_rn(p * Q_SCALE);
    // ci * 2^26 + (2^52 + pi)  ->  IMAD.WIDE-friendly form
    return (unsigned long long)ci * (1ull << CLEAN_SHIFT) +
           ((1ull << CNT_SHIFT) + (unsigned long long)pi);
}

__global__ __launch_bounds__(THREADS)
void fused_kernel(const float* __restrict__ clean,
                  const float* __restrict__ pred,
                  const int* __restrict__ ids,
                  float* __restrict__ out) {
    __shared__ unsigned long long sh[NSEG];
    __shared__ int s_is_last;
    __shared__ float sbuf[16][8];

    const int tid = threadIdx.x;
    for (int i = tid; i < NSEG; i += THREADS) sh[i] = 0ull;
    __syncthreads();

    // ---------------- histogram phase ----------------
    const int b = blockIdx.y;
    const size_t base = (size_t)b * HW + (size_t)blockIdx.x * PIX_PER_BLOCK;
    const float4* __restrict__ c4 = (const float4*)(clean + base);
    const float4* __restrict__ p4 = (const float4*)(pred + base);
    const int4* __restrict__ i4 = (const int4*)(ids + base);

#pragma unroll
    for (int it = 0; it < VEC_ITERS; ++it) {
        const int idx = it * THREADS + tid;
        const float4 c = c4[idx];
        const float4 p = p4[idx];
        const int4 id = i4[idx];
        atomicAdd(&sh[id.x], pack_pix(c.x, p.x));
        atomicAdd(&sh[id.y], pack_pix(c.y, p.y));
        atomicAdd(&sh[id.z], pack_pix(c.z, p.z));
        atomicAdd(&sh[id.w], pack_pix(c.w, p.w));
    }
    __syncthreads();

    // flush block-private histogram to global
    unsigned long long* gh = g_hist + (size_t)b * NSEG;
    for (int i = tid; i < NSEG; i += THREADS) {
        unsigned long long v = sh[i];
        if (v) atomicAdd(&gh[i], v);
    }
    __syncthreads();

    // ---------------- last-block election ----------------
    if (tid == 0) {
        __threadfence();
        unsigned int old = atomicAdd(&g_ticket, 1u);
        s_is_last = (old == TOTAL_BLOCKS - 1) ? 1 : 0;
    }
    __syncthreads();
    if (!s_is_last) return;

    // ---------------- finalize (runs in exactly one block) ----------------
    __threadfence();
    const int lane = tid & 31;
    const int warp = tid >> 5;

    float sum_loss = 0.f, nvalid = 0.f;
    float sum_t = 0.f, cnt_t = 0.f, sum_n = 0.f, cnt_n = 0.f;

    for (int bb = 0; bb < NBATCH; ++bb) {
        // bypass L1 — these lines were written by other SMs' atomics
        const unsigned long long v = __ldcg(&g_hist[bb * NSEG + tid + 1]);
        const float cntf = (float)(unsigned int)(v >> CNT_SHIFT);
        const float inv = 1.0f / fmaxf(cntf, 1.0f);
        const float cm =
            (float)(unsigned int)((v >> CLEAN_SHIFT) & FIELD_MASK) * (1.0f / Q_SCALE) * inv;
        const float pm =
            (float)(unsigned int)(v & FIELD_MASK) * (1.0f / Q_SCALE) * inv;

        const bool valid = cntf >= 8.0f;
        const bool tumor = valid && (cm >= 0.7f);
        const bool normal = valid && (cm <= 0.3f);
        const bool enh = tumor || normal;
        const bool pres = valid && !enh;

        float target = cm;
        if (tumor) target = fminf(cm + 0.08f, 1.0f);
        if (normal) target = fmaxf(cm - 0.08f, 0.0f);
        const float d = pm - target;
        const float ad = fabsf(d);
        const float sl = (ad < 1.0f) ? 0.5f * d * d : ad - 0.5f;

        const bool tm = valid && (pm > 0.5f);
        const bool nm = valid && !(pm > 0.5f);

        float a[8];
        a[0] = enh ? sl : 0.f;
        a[1] = enh ? 1.f : 0.f;
        a[2] = pres ? sl : 0.f;
        a[3] = pres ? 1.f : 0.f;
        a[4] = tm ? pm : 0.f;
        a[5] = tm ? 1.f : 0.f;
        a[6] = nm ? pm : 0.f;
        a[7] = nm ? 1.f : 0.f;

#pragma unroll
        for (int q = 0; q < 8; ++q) {
            float x = a[q];
#pragma unroll
            for (int o = 16; o > 0; o >>= 1) x += __shfl_down_sync(0xffffffffu, x, o);
            if (lane == 0) sbuf[warp][q] = x;
        }
        __syncthreads();

        if (tid == 0) {
            float r[8];
#pragma unroll
            for (int q = 0; q < 8; ++q) r[q] = 0.f;
            for (int w = 0; w < 16; ++w)
#pragma unroll
                for (int q = 0; q < 8; ++q) r[q] += sbuf[w][q];

            const float loss_enh = r[0] / fmaxf(r[1], 1.0f);
            const float loss_pres = r[2] / fmaxf(r[3], 1.0f);
            const float has_e = (r[1] > 0.f) ? 1.f : 0.f;
            const float has_p = (r[3] > 0.f) ? 1.f : 0.f;
            const float cnt = has_e + has_p;
            const float loss_b =
                (loss_enh * has_e + 0.5f * loss_pres * has_p) / fmaxf(cnt, 1.0f);
            const float valid_b = (cnt > 0.f) ? 1.f : 0.f;
            sum_loss += loss_b * valid_b;
            nvalid += valid_b;

            const float tconf = r[4] / fmaxf(r[5], 1.0f);
            const float has_t = (r[5] > 0.f) ? 1.f : 0.f;
            sum_t += tconf * has_t;
            cnt_t += has_t;

            const float nconf = r[6] / fmaxf(r[7], 1.0f);
            const float has_n = (r[7] > 0.f) ? 1.f : 0.f;
            sum_n += nconf * has_n;
            cnt_n += has_n;
        }
        __syncthreads();
    }

    // restore zeros for the next invocation / graph replay (covers ALL entries,
    // including background column 0 that the reduction never reads)
    for (int i = tid; i < NBATCH * NSEG; i += THREADS) g_hist[i] = 0ull;

    if (tid == 0) {
        g_ticket = 0u;

        float loss_prob = sum_loss / fmaxf(nvalid, 1.0f);
        float avg_t = (cnt_t > 0.f) ? (sum_t / fmaxf(cnt_t, 1.0f)) : -1.0f;
        float avg_n = (cnt_n > 0.f) ? (sum_n / fmaxf(cnt_n, 1.0f)) : -1.0f;
        const bool any_valid = nvalid > 0.f;
        if (!any_valid) {
            loss_prob = 0.0f;
            avg_t = -1.0f;
            avg_n = -1.0f;
        }
        out[0] = loss_prob;
        out[1] = 0.0f;
        out[2] = avg_t;
        out[3] = avg_n;
    }
}

extern "C" void kernel_launch(void* const* d_in, const int* in_sizes, int n_in,
                              void* d_out, int out_size) {
    const float* clean = (const float*)d_in[0];
    const float* pred = (const float*)d_in[1];
    const int* ids = (const int*)d_in[2];
    float* out = (float*)d_out;

    dim3 grid(BLOCKS_PER_BATCH, NBATCH);
    fused_kernel<<<grid, THREADS>>>(clean, pred, ids, out);
}

// round 3
// speedup vs baseline: 1.3711x; 1.3711x over previous
#include <cuda_runtime.h>
#include <cstdint>

// Problem constants
#define NSEG 513
#define NBATCH 8
#define HW (1024 * 1024)

#define BLOCKS_PER_BATCH 128
#define THREADS 256
#define PIX_PER_BLOCK (HW / BLOCKS_PER_BATCH)      // 8192
#define VEC_ITERS (PIX_PER_BLOCK / (THREADS * 4))  // 8

// Fixed-point packing: [count:12 | clean_q14:26 | pred_q14:26]
#define Q_SCALE 16384.0f
#define FIELD_MASK 0x3FFFFFFull
#define CNT_SHIFT 52
#define CLEAN_SHIFT 26

// Global scratch — zero-initialized at module load; finalize_kernel re-zeroes it
// at the end of every invocation, so the correctness run and every graph replay
// all observe zeros on entry. Deterministic, allocation-free.
__device__ unsigned long long g_hist[NBATCH * NSEG];

__device__ __forceinline__ unsigned long long pack_pix(float c, float p) {
    unsigned int ci = __float2uint_rn(c * Q_SCALE);
    unsigned int pi = __float2uint_rn(p * Q_SCALE);
    return (unsigned long long)ci * (1ull << CLEAN_SHIFT) +
           ((1ull << CNT_SHIFT) + (unsigned long long)pi);
}

__global__ __launch_bounds__(THREADS)
void hist_kernel(const float* __restrict__ clean,
                 const float* __restrict__ pred,
                 const int* __restrict__ ids) {
    __shared__ unsigned long long sh[NSEG];
    const int tid = threadIdx.x;
    for (int i = tid; i < NSEG; i += THREADS) sh[i] = 0ull;
    __syncthreads();

    const int b = blockIdx.y;
    const size_t base = (size_t)b * HW + (size_t)blockIdx.x * PIX_PER_BLOCK;
    const float4* __restrict__ c4 = (const float4*)(clean + base);
    const float4* __restrict__ p4 = (const float4*)(pred + base);
    const int4* __restrict__ i4 = (const int4*)(ids + base);

#pragma unroll
    for (int it = 0; it < VEC_ITERS; ++it) {
        const int idx = it * THREADS + tid;
        const float4 c = c4[idx];
        const float4 p = p4[idx];
        const int4 id = i4[idx];
        atomicAdd(&sh[id.x], pack_pix(c.x, p.x));
        atomicAdd(&sh[id.y], pack_pix(c.y, p.y));
        atomicAdd(&sh[id.z], pack_pix(c.z, p.z));
        atomicAdd(&sh[id.w], pack_pix(c.w, p.w));
    }
    __syncthreads();

    unsigned long long* gh = g_hist + (size_t)b * NSEG;
    for (int i = tid; i < NSEG; i += THREADS) {
        unsigned long long v = sh[i];
        if (v) atomicAdd(&gh[i], v);
    }
}

// One block, 512 threads: thread t handles segment t+1 (segment 0 = background,
// always invalid). Re-zeroes g_hist at the end for the next invocation.
__global__ __launch_bounds__(512)
void finalize_kernel(float* __restrict__ out) {
    __shared__ float sbuf[16][8];
    const int tid = threadIdx.x;
    const int lane = tid & 31;
    const int warp = tid >> 5;

    float sum_loss = 0.f, nvalid = 0.f;
    float sum_t = 0.f, cnt_t = 0.f, sum_n = 0.f, cnt_n = 0.f;

    for (int b = 0; b < NBATCH; ++b) {
        const unsigned long long v = g_hist[b * NSEG + tid + 1];
        const float cntf = (float)(unsigned int)(v >> CNT_SHIFT);
        const float inv = 1.0f / fmaxf(cntf, 1.0f);
        const float cm =
            (float)(unsigned int)((v >> CLEAN_SHIFT) & FIELD_MASK) * (1.0f / Q_SCALE) * inv;
        const float pm =
            (float)(unsigned int)(v & FIELD_MASK) * (1.0f / Q_SCALE) * inv;

        const bool valid = cntf >= 8.0f;
        const bool tumor = valid && (cm >= 0.7f);
        const bool normal = valid && (cm <= 0.3f);
        const bool enh = tumor || normal;
        const bool pres = valid && !enh;

        float target = cm;
        if (tumor) target = fminf(cm + 0.08f, 1.0f);
        if (normal) target = fmaxf(cm - 0.08f, 0.0f);
        const float d = pm - target;
        const float ad = fabsf(d);
        const float sl = (ad < 1.0f) ? 0.5f * d * d : ad - 0.5f;

        const bool tm = valid && (pm > 0.5f);
        const bool nm = valid && !(pm > 0.5f);

        float a[8];
        a[0] = enh ? sl : 0.f;
        a[1] = enh ? 1.f : 0.f;
        a[2] = pres ? sl : 0.f;
        a[3] = pres ? 1.f : 0.f;
        a[4] = tm ? pm : 0.f;
        a[5] = tm ? 1.f : 0.f;
        a[6] = nm ? pm : 0.f;
        a[7] = nm ? 1.f : 0.f;

#pragma unroll
        for (int q = 0; q < 8; ++q) {
            float x = a[q];
#pragma unroll
            for (int o = 16; o > 0; o >>= 1) x += __shfl_down_sync(0xffffffffu, x, o);
            if (lane == 0) sbuf[warp][q] = x;
        }
        __syncthreads();

        if (tid == 0) {
            float r[8];
#pragma unroll
            for (int q = 0; q < 8; ++q) r[q] = 0.f;
            for (int w = 0; w < 16; ++w)
#pragma unroll
                for (int q = 0; q < 8; ++q) r[q] += sbuf[w][q];

            const float loss_enh = r[0] / fmaxf(r[1], 1.0f);
            const float loss_pres = r[2] / fmaxf(r[3], 1.0f);
            const float has_e = (r[1] > 0.f) ? 1.f : 0.f;
            const float has_p = (r[3] > 0.f) ? 1.f : 0.f;
            const float cnt = has_e + has_p;
            const float loss_b =
                (loss_enh * has_e + 0.5f * loss_pres * has_p) / fmaxf(cnt, 1.0f);
            const float valid_b = (cnt > 0.f) ? 1.f : 0.f;
            sum_loss += loss_b * valid_b;
            nvalid += valid_b;

            const float tconf = r[4] / fmaxf(r[5], 1.0f);
            const float has_t = (r[5] > 0.f) ? 1.f : 0.f;
            sum_t += tconf * has_t;
            cnt_t += has_t;

            const float nconf = r[6] / fmaxf(r[7], 1.0f);
            const float has_n = (r[7] > 0.f) ? 1.f : 0.f;
            sum_n += nconf * has_n;
            cnt_n += has_n;
        }
        __syncthreads();
    }

    // restore zeros for the next invocation / graph replay
    for (int i = tid; i < NBATCH * NSEG; i += 512) g_hist[i] = 0ull;

    if (tid == 0) {
        float loss_prob = sum_loss / fmaxf(nvalid, 1.0f);
        float avg_t = (cnt_t > 0.f) ? (sum_t / fmaxf(cnt_t, 1.0f)) : -1.0f;
        float avg_n = (cnt_n > 0.f) ? (sum_n / fmaxf(cnt_n, 1.0f)) : -1.0f;
        const bool any_valid = nvalid > 0.f;
        if (!any_valid) {
            loss_prob = 0.0f;
            avg_t = -1.0f;
            avg_n = -1.0f;
        }
        out[0] = loss_prob;
        out[1] = 0.0f;
        out[2] = avg_t;
        out[3] = avg_n;
    }
}

extern "C" void kernel_launch(void* const* d_in, const int* in_sizes, int n_in,
                              void* d_out, int out_size) {
    const float* clean = (const float*)d_in[0];
    const float* pred = (const float*)d_in[1];
    const int* ids = (const int*)d_in[2];
    float* out = (float*)d_out;

    dim3 grid(BLOCKS_PER_BATCH, NBATCH);
    hist_kernel<<<grid, THREADS>>>(clean, pred, ids);
    finalize_kernel<<<1, 512>>>(out);
}

// round 4
// speedup vs baseline: 1.5412x; 1.1240x over previous
#include <cuda_runtime.h>
#include <cstdint>

// Problem constants
#define NSEG 513
#define NBATCH 8
#define HW (1024 * 1024)

#define BLOCKS_PER_BATCH 128
#define THREADS 256
#define PIX_PER_BLOCK (HW / BLOCKS_PER_BATCH)      // 8192
#define VEC_ITERS (PIX_PER_BLOCK / (THREADS * 4))  // 8

// Fixed-point packing: [count:12 | clean_q14:26 | pred_q14:26]
#define Q_SCALE 16384.0f
#define FIELD_MASK 0x3FFFFFFull
#define CNT_SHIFT 52
#define CLEAN_SHIFT 26

// Global scratch — zero-initialized at module load; finalize_kernel re-zeroes it
// at the end of every invocation, so the correctness run and every graph replay
// all observe zeros on entry. Deterministic, allocation-free.
__device__ unsigned long long g_hist[NBATCH * NSEG];

__device__ __forceinline__ unsigned long long pack_pix(float c, float p) {
    unsigned int ci = __float2uint_rn(c * Q_SCALE);
    unsigned int pi = __float2uint_rn(p * Q_SCALE);
    return (unsigned long long)ci * (1ull << CLEAN_SHIFT) +
           ((1ull << CNT_SHIFT) + (unsigned long long)pi);
}

__global__ __launch_bounds__(THREADS)
void hist_kernel(const float* __restrict__ clean,
                 const float* __restrict__ pred,
                 const int* __restrict__ ids) {
    __shared__ unsigned long long sh[NSEG];
    const int tid = threadIdx.x;
    for (int i = tid; i < NSEG; i += THREADS) sh[i] = 0ull;
    __syncthreads();

    const int b = blockIdx.y;
    const size_t base = (size_t)b * HW + (size_t)blockIdx.x * PIX_PER_BLOCK;
    const float4* __restrict__ c4 = (const float4*)(clean + base);
    const float4* __restrict__ p4 = (const float4*)(pred + base);
    const int4* __restrict__ i4 = (const int4*)(ids + base);

#pragma unroll
    for (int it = 0; it < VEC_ITERS; ++it) {
        const int idx = it * THREADS + tid;
        const float4 c = c4[idx];
        const float4 p = p4[idx];
        const int4 id = i4[idx];
        atomicAdd(&sh[id.x], pack_pix(c.x, p.x));
        atomicAdd(&sh[id.y], pack_pix(c.y, p.y));
        atomicAdd(&sh[id.z], pack_pix(c.z, p.z));
        atomicAdd(&sh[id.w], pack_pix(c.w, p.w));
    }
    __syncthreads();

    unsigned long long* gh = g_hist + (size_t)b * NSEG;
    for (int i = tid; i < NSEG; i += THREADS) {
        unsigned long long v = sh[i];
        if (v) atomicAdd(&gh[i], v);
    }
}

// Latency-flat finalize: 16 warps; warp w owns batch w/2, half (w&1) of the
// 512 segments. Each lane accumulates 8 quantities over 8 independent loads
// (MLP=8), one warp reduction, one __syncthreads, then warp 0 combines the 8
// batches in parallel (one lane per batch) and shuffle-reduces.
__global__ __launch_bounds__(512)
void finalize_kernel(float* __restrict__ out) {
    __shared__ float sbuf[16][8];
    const int tid = threadIdx.x;
    const int lane = tid & 31;
    const int warp = tid >> 5;
    const int b = warp >> 1;
    const int half = warp & 1;

    float acc[8];
#pragma unroll
    for (int q = 0; q < 8; ++q) acc[q] = 0.f;

#pragma unroll
    for (int it = 0; it < 8; ++it) {
        const int seg = 1 + half * 256 + it * 32 + lane;
        const unsigned long long v = __ldcg(&g_hist[b * NSEG + seg]);

        const float cntf = (float)(unsigned int)(v >> CNT_SHIFT);
        const float inv = 1.0f / fmaxf(cntf, 1.0f);
        const float cm =
            (float)(unsigned int)((v >> CLEAN_SHIFT) & FIELD_MASK) * (1.0f / Q_SCALE) * inv;
        const float pm =
            (float)(unsigned int)(v & FIELD_MASK) * (1.0f / Q_SCALE) * inv;

        const bool valid = cntf >= 8.0f;
        const bool tumor = valid && (cm >= 0.7f);
        const bool normal = valid && (cm <= 0.3f);
        const bool enh = tumor || normal;
        const bool pres = valid && !enh;

        float target = cm;
        if (tumor) target = fminf(cm + 0.08f, 1.0f);
        if (normal) target = fmaxf(cm - 0.08f, 0.0f);
        const float d = pm - target;
        const float ad = fabsf(d);
        const float sl = (ad < 1.0f) ? 0.5f * d * d : ad - 0.5f;

        const bool tm = valid && (pm > 0.5f);
        const bool nm = valid && !(pm > 0.5f);

        acc[0] += enh ? sl : 0.f;
        acc[1] += enh ? 1.f : 0.f;
        acc[2] += pres ? sl : 0.f;
        acc[3] += pres ? 1.f : 0.f;
        acc[4] += tm ? pm : 0.f;
        acc[5] += tm ? 1.f : 0.f;
        acc[6] += nm ? pm : 0.f;
        acc[7] += nm ? 1.f : 0.f;
    }

#pragma unroll
    for (int q = 0; q < 8; ++q) {
        float x = acc[q];
#pragma unroll
        for (int o = 16; o > 0; o >>= 1) x += __shfl_down_sync(0xffffffffu, x, o);
        if (lane == 0) sbuf[warp][q] = x;
    }
    __syncthreads();

    if (warp == 0) {
        // lane l < 8 handles batch l; lanes >= 8 contribute zeros
        const int bb = (lane < 8) ? lane : 0;
        float r[8];
#pragma unroll
        for (int q = 0; q < 8; ++q)
            r[q] = sbuf[2 * bb][q] + sbuf[2 * bb + 1][q];

        float loss_term = 0.f, valid_b = 0.f, t_term = 0.f, has_t = 0.f,
              n_term = 0.f, has_n = 0.f;
        if (lane < 8) {
            const float loss_enh = r[0] / fmaxf(r[1], 1.0f);
            const float loss_pres = r[2] / fmaxf(r[3], 1.0f);
            const float has_e = (r[1] > 0.f) ? 1.f : 0.f;
            const float has_p = (r[3] > 0.f) ? 1.f : 0.f;
            const float cnt = has_e + has_p;
            const float loss_b =
                (loss_enh * has_e + 0.5f * loss_pres * has_p) / fmaxf(cnt, 1.0f);
            valid_b = (cnt > 0.f) ? 1.f : 0.f;
            loss_term = loss_b * valid_b;

            has_t = (r[5] > 0.f) ? 1.f : 0.f;
            t_term = (r[4] / fmaxf(r[5], 1.0f)) * has_t;
            has_n = (r[7] > 0.f) ? 1.f : 0.f;
            n_term = (r[6] / fmaxf(r[7], 1.0f)) * has_n;
        }

#pragma unroll
        for (int o = 4; o > 0; o >>= 1) {
            loss_term += __shfl_down_sync(0xffffffffu, loss_term, o);
            valid_b += __shfl_down_sync(0xffffffffu, valid_b, o);
            t_term += __shfl_down_sync(0xffffffffu, t_term, o);
            has_t += __shfl_down_sync(0xffffffffu, has_t, o);
            n_term += __shfl_down_sync(0xffffffffu, n_term, o);
            has_n += __shfl_down_sync(0xffffffffu, has_n, o);
        }

        if (lane == 0) {
            float loss_prob = loss_term / fmaxf(valid_b, 1.0f);
            float avg_t = (has_t > 0.f) ? (t_term / fmaxf(has_t, 1.0f)) : -1.0f;
            float avg_n = (has_n > 0.f) ? (n_term / fmaxf(has_n, 1.0f)) : -1.0f;
            if (!(valid_b > 0.f)) {
                loss_prob = 0.0f;
                avg_t = -1.0f;
                avg_n = -1.0f;
            }
            out[0] = loss_prob;
            out[1] = 0.0f;
            out[2] = avg_t;
            out[3] = avg_n;
        }
    }

    // restore zeros for the next invocation / graph replay
    for (int i = tid; i < NBATCH * NSEG; i += 512) g_hist[i] = 0ull;
}

extern "C" void kernel_launch(void* const* d_in, const int* in_sizes, int n_in,
                              void* d_out, int out_size) {
    const float* clean = (const float*)d_in[0];
    const float* pred = (const float*)d_in[1];
    const int* ids = (const int*)d_in[2];
    float* out = (float*)d_out;

    dim3 grid(BLOCKS_PER_BATCH, NBATCH);
    hist_kernel<<<grid, THREADS>>>(clean, pred, ids);
    finalize_kernel<<<1, 512>>>(out);
}